// round 9
// baseline (speedup 1.0000x reference)
#include <cuda_runtime.h>
#include <math.h>

#define B_    16
#define C_    256
#define HIDE_ 128
#define HW_   16384
#define HW4_  4096            // float4 per row
#define ROWS_ (B_*C_)         // 4096
#define LAG_  2               // CTA group g scales batch g-LAG_
#define NGROUPS_ (B_ + LAG_)  // 18

__device__ float g_mean[ROWS_];
__device__ float g_gate[ROWS_];
__device__ int   g_cnt[B_];          // reduce arrivals  (zero-init, self-reset)
__device__ int   g_done[B_];         // scale arrivals   (zero-init, self-reset)
__device__ volatile int g_flag[B_];  // gate ready       (zero-init, self-reset)

__global__ void __launch_bounds__(256)
k_pipe(const float* __restrict__ x,
       const float* __restrict__ w1,
       const float* __restrict__ w2p,
       const float* __restrict__ w3p,
       const float* __restrict__ w4,
       const float* __restrict__ A2,
       float* __restrict__ out) {
    const int g = blockIdx.x >> 8;       // group 0..17
    const int r = blockIdx.x & 255;      // row within batch
    const int t = threadIdx.x;

    __shared__ __align__(16) float mean_s[C_];
    __shared__ __align__(16) float y_s[HIDE_];
    __shared__ __align__(16) float z_s[HIDE_];
    __shared__ __align__(16) float red[256];
    __shared__ float sm[8];
    __shared__ int   last_s;

    // ================= Phase 1: reduce row (batch g) — no dependencies =================
    if (g < B_) {
        const int row = g * C_ + r;
        const float4* xr = reinterpret_cast<const float4*>(x) + (size_t)row * HW4_;
        float s = 0.f;
        #pragma unroll
        for (int i = 0; i < 16; ++i) {
            float4 v = xr[t + i * 256];
            s += (v.x + v.y) + (v.z + v.w);
        }
        #pragma unroll
        for (int off = 16; off > 0; off >>= 1)
            s += __shfl_down_sync(0xffffffffu, s, off);
        int lane = t & 31, wid = t >> 5;
        if (lane == 0) sm[wid] = s;
        __syncthreads();
        if (t == 0) {
            float tot = 0.f;
            #pragma unroll
            for (int w = 0; w < 8; ++w) tot += sm[w];
            g_mean[row] = tot * (1.0f / (float)HW_);
            __threadfence();
            int old = atomicAdd(&g_cnt[g], 1);
            last_s = (old == C_ - 1);
        }
        __syncthreads();

        if (last_s) {
            // -------- last reduce CTA of batch g computes the 256-wide gate --------
            __threadfence();
            mean_s[t] = __ldcg(&g_mean[g * C_ + t]);
            __syncthreads();

            const float w2 = *w2p;
            const float w3 = *w3p;

            if (t < HIDE_) {
                const float4* wr = reinterpret_cast<const float4*>(w1 + (size_t)t * C_);
                const float4* ms = reinterpret_cast<const float4*>(mean_s);
                float acc = 0.f;
                #pragma unroll 16
                for (int k = 0; k < C_ / 4; ++k) {
                    float4 w = wr[k];
                    float4 m = ms[k];
                    acc = fmaf(m.x, w.x, acc);
                    acc = fmaf(m.y, w.y, acc);
                    acc = fmaf(m.z, w.z, acc);
                    acc = fmaf(m.w, w.w, acc);
                }
                y_s[t] = acc;
            }
            __syncthreads();

            float v = (t < HIDE_) ? w2 * y_s[t] : -INFINITY;
            red[t] = v;
            __syncthreads();
            #pragma unroll
            for (int off = 128; off > 0; off >>= 1) {
                if (t < off) red[t] = fmaxf(red[t], red[t + off]);
                __syncthreads();
            }
            float m = red[0];
            __syncthreads();
            float e = (t < HIDE_) ? __expf(v - m) : 0.f;
            red[t] = e;
            __syncthreads();
            #pragma unroll
            for (int off = 128; off > 0; off >>= 1) {
                if (t < off) red[t] += red[t + off];
                __syncthreads();
            }
            float inv_sum = 1.0f / red[0];
            __syncthreads();

            if (t < HIDE_) {
                float acc = 0.f;
                #pragma unroll 8
                for (int k = 0; k < HIDE_; ++k) acc = fmaf(y_s[k], A2[(size_t)k * HIDE_ + t], acc);
                float y2 = y_s[t] * (e * inv_sum) + acc;
                z_s[t] = fmaxf(w3 * y2, 0.f);
            }
            __syncthreads();

            {
                const float4* wr = reinterpret_cast<const float4*>(w4 + (size_t)t * HIDE_);
                const float4* zs = reinterpret_cast<const float4*>(z_s);
                float acc = 0.f;
                #pragma unroll 16
                for (int k = 0; k < HIDE_ / 4; ++k) {
                    float4 w = wr[k];
                    float4 z = zs[k];
                    acc = fmaf(z.x, w.x, acc);
                    acc = fmaf(z.y, w.y, acc);
                    acc = fmaf(z.z, w.z, acc);
                    acc = fmaf(z.w, w.w, acc);
                }
                g_gate[g * C_ + t] = 1.0f / (1.0f + __expf(-acc));
            }
            __syncthreads();
            if (t == 0) {
                g_cnt[g] = 0;            // self-reset for next replay
                __threadfence();         // release: gate before flag
                g_flag[g] = 1;
            }
        }
    }

    // ================= Phase 2: scale row (batch g-LAG) — gate almost surely ready =================
    if (g >= LAG_) {
        const int b = g - LAG_;
        const int row = b * C_ + r;

        if (t == 0) {
            while (g_flag[b] == 0) __nanosleep(32);
            __threadfence();             // acquire before reading g_gate
        }
        __syncthreads();

        float gt = __ldcg(&g_gate[row]);
        const float4* x4 = reinterpret_cast<const float4*>(x) + (size_t)row * HW4_;
        float4* o4 = reinterpret_cast<float4*>(out) + (size_t)row * HW4_;
        #pragma unroll
        for (int i = 0; i < 16; ++i) {
            int idx = t + i * 256;
            float4 v = __ldcg(&x4[idx]);   // expected L2 hit (reduced ~512 CTAs ago)
            v.x *= gt; v.y *= gt; v.z *= gt; v.w *= gt;
            __stcs(&o4[idx], v);           // evict-first: don't displace x
        }

        if (t == 0) {
            int old = atomicAdd(&g_done[b], 1);
            if (old == C_ - 1) {           // last scaler: reset for next replay
                g_done[b] = 0;
                g_flag[b] = 0;
            }
        }
    }
}

extern "C" void kernel_launch(void* const* d_in, const int* in_sizes, int n_in,
                              void* d_out, int out_size) {
    const float* x  = (const float*)d_in[0];
    const float* w1 = (const float*)d_in[1];
    const float* w2 = (const float*)d_in[2];
    const float* w3 = (const float*)d_in[3];
    const float* w4 = (const float*)d_in[4];
    const float* A2 = (const float*)d_in[5];
    float* out = (float*)d_out;

    k_pipe<<<NGROUPS_ * C_, 256>>>(x, w1, w2, w3, w4, A2, out);
}